// round 14
// baseline (speedup 1.0000x reference)
#include <cuda_runtime.h>

// Geometry: thread owns 4 rows x 4 cols (one float4 quad per row).
// Warp = 32 quads = 128 px wide. Block = 8 warps x 4 rows = 32 rows.
// Occupancy 2 (full 128-reg budget) + 1-deep pipeline on the DRAM stream.
#define HH   512
#define W4   128             // quads (float4) per row
#define FR   (HH * W4)       // quads per channel-frame
#define FS   (2 * FR)        // quads per timestep
#define TC   9               // t-chunks
#define TPC  22              // 198 / 9
#define GX   4               // 128 quads / 32 lanes
#define GY   16              // 512 rows / 32 rows-per-block
#define NBLK (GX * GY * TC)  // 576

#define DENOM 52107462.0     // 198 * 513 * 513
#define SCALE 6400.0         // (1/DT)^2 deferred from the residual

typedef unsigned long long u64;

__device__ float g_part[NBLK * 2];
__device__ unsigned int g_count = 0;

// ---------- packed f32x2 helpers ----------
__device__ __forceinline__ u64 pk(float a, float b) {
    u64 r; asm("mov.b64 %0, {%1, %2};" : "=l"(r) : "f"(a), "f"(b)); return r;
}
__device__ __forceinline__ void upk(u64 v, float& a, float& b) {
    asm("mov.b64 {%0, %1}, %2;" : "=f"(a), "=f"(b) : "l"(v));
}
__device__ __forceinline__ u64 fadd2(u64 a, u64 b) {
    u64 d; asm("add.rn.f32x2 %0, %1, %2;" : "=l"(d) : "l"(a), "l"(b)); return d;
}
__device__ __forceinline__ u64 fsub2(u64 a, u64 b) {
    u64 d; asm("sub.rn.f32x2 %0, %1, %2;" : "=l"(d) : "l"(a), "l"(b)); return d;
}
__device__ __forceinline__ u64 fmul2(u64 a, u64 b) {
    u64 d; asm("mul.rn.f32x2 %0, %1, %2;" : "=l"(d) : "l"(a), "l"(b)); return d;
}
__device__ __forceinline__ u64 ffma2(u64 a, u64 b, u64 c) {
    u64 d; asm("fma.rn.f32x2 %0, %1, %2, %3;" : "=l"(d) : "l"(a), "l"(b), "l"(c)); return d;
}

// One quad-row, both channels -> packed residual pairs (rul=px0/1, ruh=px2/3).
__device__ __forceinline__ void quad_residual(
    ulonglong2 cu, ulonglong2 cv,
    u64 Lhu, u64 Rlu, u64 Lhv, u64 Rlv,
    ulonglong2 um1, ulonglong2 up1, ulonglong2 um2, ulonglong2 up2,
    ulonglong2 vm1, ulonglong2 vp1, ulonglong2 vm2, ulonglong2 vp2,
    ulonglong2 nu, ulonglong2 nv,
    u64 CC, u64 CN, u64 CF, u64 MDT,
    u64& rul, u64& ruh, u64& rvl, u64& rvh)
{
    float l0, l1, c0, c1, c2, c3, r0, r1;

    // ---- u laplacian (MU-folded)
    upk(Lhu, l0, l1); upk(cu.x, c0, c1); upk(cu.y, c2, c3); upk(Rlu, r0, r1);
    {
        const u64 m1 = pk(l1, c0);
        const u64 m2 = pk(c1, c2);
        const u64 m3 = pk(c3, r0);
        const u64 nearlo = fadd2(fadd2(m1, m2), fadd2(um1.x, up1.x));
        const u64 nearhi = fadd2(fadd2(m2, m3), fadd2(um1.y, up1.y));
        const u64 farlo  = fadd2(fadd2(Lhu, cu.y), fadd2(um2.x, up2.x));
        const u64 farhi  = fadd2(fadd2(cu.x, Rlu), fadd2(um2.y, up2.y));
        rul = ffma2(CN, nearlo, ffma2(CF, farlo, fmul2(CC, cu.x)));  // lapUlo
        ruh = ffma2(CN, nearhi, ffma2(CF, farhi, fmul2(CC, cu.y)));  // lapUhi
    }
    // ---- v laplacian
    upk(Lhv, l0, l1); upk(cv.x, c0, c1); upk(cv.y, c2, c3); upk(Rlv, r0, r1);
    {
        const u64 m1 = pk(l1, c0);
        const u64 m2 = pk(c1, c2);
        const u64 m3 = pk(c3, r0);
        const u64 nearlo = fadd2(fadd2(m1, m2), fadd2(vm1.x, vp1.x));
        const u64 nearhi = fadd2(fadd2(m2, m3), fadd2(vm1.y, vp1.y));
        const u64 farlo  = fadd2(fadd2(Lhv, cv.y), fadd2(vm2.x, vp2.x));
        const u64 farhi  = fadd2(fadd2(cv.x, Rlv), fadd2(vm2.y, vp2.y));
        rvl = ffma2(CN, nearlo, ffma2(CF, farlo, fmul2(CC, cv.x)));  // lapVlo
        rvh = ffma2(CN, nearhi, ffma2(CF, farhi, fmul2(CC, cv.y)));  // lapVhi
    }

    // ---- residuals: r = (n - c) - DT*(c + lap + s*(±...))
    {
        const u64 sl = ffma2(cu.x, cu.x, fmul2(cv.x, cv.x));
        const u64 sh = ffma2(cu.y, cu.y, fmul2(cv.y, cv.y));
        const u64 Xul = fadd2(cu.x, ffma2(sl, fsub2(cv.x, cu.x), rul));
        const u64 Xuh = fadd2(cu.y, ffma2(sh, fsub2(cv.y, cu.y), ruh));
        const u64 Xvl = fadd2(cv.x, fsub2(rvl, fmul2(sl, fadd2(cv.x, cu.x))));
        const u64 Xvh = fadd2(cv.y, fsub2(rvh, fmul2(sh, fadd2(cv.y, cu.y))));
        rul = ffma2(Xul, MDT, fsub2(nu.x, cu.x));
        ruh = ffma2(Xuh, MDT, fsub2(nu.y, cu.y));
        rvl = ffma2(Xvl, MDT, fsub2(nv.x, cv.x));
        rvh = ffma2(Xvh, MDT, fsub2(nv.y, cv.y));
    }
}

__global__ __launch_bounds__(256, 2)
void pde_kernel(const float* __restrict__ inF, float* __restrict__ out)
{
    const int tx = threadIdx.x;               // lane
    const int ty = threadIdx.y;               // warp (0..7)
    const int jb = blockIdx.x * 32 + tx;      // quad column 0..127
    const int i0 = blockIdx.y * 32 + ty * 4;  // first of 4 rows
    const int t0 = blockIdx.z * TPC;

    const ulonglong2* __restrict__ base = (const ulonglong2*)inF;

    // single advancing base pointer + loop-invariant int offsets (quad units)
    const ulonglong2* pC = base + (size_t)t0 * FS + i0 * W4 + jb;
    const int om2 = (((i0 - 2) & 511) - i0) * W4;
    const int om1 = (((i0 - 1) & 511) - i0) * W4;
    const int op4 = (((i0 + 4) & 511) - i0) * W4;
    const int op5 = (((i0 + 5) & 511) - i0) * W4;

    // edge-lane horizontal neighbor (u64 granularity):
    // lane0 -> left quad's HI u64; lane31 -> right quad's LO u64.
    const int eq = ((tx == 31) ? (jb + 1) : (jb - 1)) & 127;
    const u64* pE = (const u64*)(base + (size_t)t0 * FS + i0 * W4 + eq) + ((tx == 0) ? 1 : 0);
    const bool isedge = (tx == 0) | (tx == 31);

    // constants (MU and DX^2 folded; 1/DT deferred)
    const float ccf = 0.1f * (-5.0f) * 25.0f;
    const float cnf = 0.1f * (4.0f / 3.0f) * 25.0f;
    const float cff = 0.1f * (-1.0f / 12.0f) * 25.0f;
    const u64 CC  = pk(ccf, ccf);
    const u64 CN  = pk(cnf, cnf);
    const u64 CF  = pk(cff, cff);
    const u64 MDT = pk(-0.0125f, -0.0125f);

    const bool rowdup = (i0 == 0);            // warp-uniform

    // carried centers at time t (C): 4 rows x 2 channels (quads)
    ulonglong2 Cu0 = pC[0 * W4];
    ulonglong2 Cu1 = pC[1 * W4];
    ulonglong2 Cu2 = pC[2 * W4];
    ulonglong2 Cu3 = pC[3 * W4];
    ulonglong2 Cv0 = pC[FR + 0 * W4];
    ulonglong2 Cv1 = pC[FR + 1 * W4];
    ulonglong2 Cv2 = pC[FR + 2 * W4];
    ulonglong2 Cv3 = pC[FR + 3 * W4];

    // pipeline buffer: centers at t+1 (N), preloaded
    ulonglong2 Nu0 = pC[FS + 0 * W4];
    ulonglong2 Nu1 = pC[FS + 1 * W4];
    ulonglong2 Nu2 = pC[FS + 2 * W4];
    ulonglong2 Nu3 = pC[FS + 3 * W4];
    ulonglong2 Nv0 = pC[FS + FR + 0 * W4];
    ulonglong2 Nv1 = pC[FS + FR + 1 * W4];
    ulonglong2 Nv2 = pC[FS + FR + 2 * W4];
    ulonglong2 Nv3 = pC[FS + FR + 3 * W4];

    u64 aUl = 0, aUh = 0, aVl = 0, aVh = 0;

    #pragma unroll 2
    for (int it = 0; it < TPC; ++it) {
        // ---- prefetch centers at t+2 (DRAM stream, consumed NEXT iteration).
        // Safe: max frame index touched = 176+21+2 = 199 = T-1.
        const ulonglong2 Qu0 = pC[2 * FS + 0 * W4];
        const ulonglong2 Qu1 = pC[2 * FS + 1 * W4];
        const ulonglong2 Qu2 = pC[2 * FS + 2 * W4];
        const ulonglong2 Qu3 = pC[2 * FS + 3 * W4];
        const ulonglong2 Qv0 = pC[2 * FS + FR + 0 * W4];
        const ulonglong2 Qv1 = pC[2 * FS + FR + 1 * W4];
        const ulonglong2 Qv2 = pC[2 * FS + FR + 2 * W4];
        const ulonglong2 Qv3 = pC[2 * FS + FR + 3 * W4];

        // ---- vertical halo rows at t (cache-hot)
        const ulonglong2 hm2u = pC[om2];
        const ulonglong2 hm2v = pC[om2 + FR];
        const ulonglong2 hm1u = pC[om1];
        const ulonglong2 hm1v = pC[om1 + FR];
        const ulonglong2 hp4u = pC[op4];
        const ulonglong2 hp4v = pC[op4 + FR];
        const ulonglong2 hp5u = pC[op5];
        const ulonglong2 hp5v = pC[op5 + FR];

        // edge-lane horizontal neighbors (predicated, cache-hot)
        u64 eu0 = 0, eu1 = 0, eu2 = 0, eu3 = 0;
        u64 ev0 = 0, ev1 = 0, ev2 = 0, ev3 = 0;
        if (isedge) {
            eu0 = pE[0 * 2 * W4];
            eu1 = pE[1 * 2 * W4];
            eu2 = pE[2 * 2 * W4];
            eu3 = pE[3 * 2 * W4];
            ev0 = pE[2 * FR + 0 * 2 * W4];
            ev1 = pE[2 * FR + 1 * 2 * W4];
            ev2 = pE[2 * FR + 2 * 2 * W4];
            ev3 = pE[2 * FR + 3 * 2 * W4];
        }

        // row stacks (rows i0-2 .. i0+5) at time t
        const ulonglong2 RU[8] = {hm2u, hm1u, Cu0, Cu1, Cu2, Cu3, hp4u, hp5u};
        const ulonglong2 RV[8] = {hm2v, hm1v, Cv0, Cv1, Cv2, Cv3, hp4v, hp5v};
        const ulonglong2 NUr[4] = {Nu0, Nu1, Nu2, Nu3};
        const ulonglong2 NVr[4] = {Nv0, Nv1, Nv2, Nv3};
        const u64 EU[4] = {eu0, eu1, eu2, eu3};
        const u64 EV[4] = {ev0, ev1, ev2, ev3};

        #pragma unroll
        for (int r = 0; r < 4; ++r) {
            const ulonglong2 cu = RU[r + 2];
            const ulonglong2 cv = RV[r + 2];

            // horizontal neighbors via warp shuffle (edge lanes from gmem)
            u64 Lhu = __shfl_up_sync(0xffffffffu, cu.y, 1);
            u64 Lhv = __shfl_up_sync(0xffffffffu, cv.y, 1);
            u64 Rlu = __shfl_down_sync(0xffffffffu, cu.x, 1);
            u64 Rlv = __shfl_down_sync(0xffffffffu, cv.x, 1);
            if (tx == 0)  { Lhu = EU[r]; Lhv = EV[r]; }
            if (tx == 31) { Rlu = EU[r]; Rlv = EV[r]; }

            u64 rul, ruh, rvl, rvh;
            quad_residual(cu, cv, Lhu, Rlu, Lhv, Rlv,
                          RU[r + 1], RU[r + 3], RU[r], RU[r + 4],
                          RV[r + 1], RV[r + 3], RV[r], RV[r + 4],
                          NUr[r], NVr[r],
                          CC, CN, CF, MDT, rul, ruh, rvl, rvh);

            aUl = ffma2(rul, rul, aUl);
            aUh = ffma2(ruh, ruh, aUh);
            aVl = ffma2(rvl, rvl, aVl);
            aVh = ffma2(rvh, rvh, aVh);

            if (r == 0 && rowdup) {              // duplicated grid row 0 (warp-uniform)
                aUl = ffma2(rul, rul, aUl);
                aUh = ffma2(ruh, ruh, aUh);
                aVl = ffma2(rvl, rvl, aVl);
                aVh = ffma2(rvh, rvh, aVh);
            }
        }

        // slide the pipeline: C <- N, N <- Q (renamed away by unroll-2)
        Cu0 = Nu0; Cu1 = Nu1; Cu2 = Nu2; Cu3 = Nu3;
        Cv0 = Nv0; Cv1 = Nv1; Cv2 = Nv2; Cv3 = Nv3;
        Nu0 = Qu0; Nu1 = Qu1; Nu2 = Qu2; Nu3 = Qu3;
        Nv0 = Qv0; Nv1 = Qv1; Nv2 = Qv2; Nv3 = Qv3;
        pC += FS;
        pE += 2 * FS;
    }

    // fold packed accumulators; duplicated grid col 0 via epilogue weight on
    // element a of the lo pair (global col 0 = px0 of quad 0).
    const float wj = (jb == 0) ? 2.0f : 1.0f;
    float a, b, c, d;
    upk(aUl, a, b); upk(aUh, c, d);
    float sum_u = wj * a + b + c + d;
    upk(aVl, a, b); upk(aVh, c, d);
    float sum_v = wj * a + b + c + d;

    #pragma unroll
    for (int off = 16; off > 0; off >>= 1) {
        sum_u += __shfl_down_sync(0xffffffffu, sum_u, off);
        sum_v += __shfl_down_sync(0xffffffffu, sum_v, off);
    }

    __shared__ float su[8], sv[8];
    __shared__ bool isLast;
    if (tx == 0) { su[ty] = sum_u; sv[ty] = sum_v; }
    __syncthreads();

    const int tid = ty * 32 + tx;
    if (tid == 0) {
        float pa = 0.0f, pb = 0.0f;
        #pragma unroll
        for (int k = 0; k < 8; ++k) { pa += su[k]; pb += sv[k]; }
        const int blk = (blockIdx.z * GY + blockIdx.y) * GX + blockIdx.x;
        g_part[blk * 2 + 0] = pa;
        g_part[blk * 2 + 1] = pb;
        __threadfence();
        const unsigned int old = atomicAdd(&g_count, 1);
        isLast = (old == (unsigned int)(NBLK - 1));
    }
    __syncthreads();

    if (isLast) {
        __threadfence();
        double da = 0.0, db = 0.0;
        for (int k = tid; k < NBLK; k += 256) {
            da += (double)g_part[2 * k + 0];
            db += (double)g_part[2 * k + 1];
        }
        __shared__ double sa[256], sb[256];
        sa[tid] = da; sb[tid] = db;
        __syncthreads();
        #pragma unroll
        for (int s = 128; s > 0; s >>= 1) {
            if (tid < s) { sa[tid] += sa[tid + s]; sb[tid] += sb[tid + s]; }
            __syncthreads();
        }
        if (tid == 0) {
            out[0] = (float)(sa[0] * SCALE / DENOM);
            out[1] = (float)(sb[0] * SCALE / DENOM);
            g_count = 0;
        }
    }
}

extern "C" void kernel_launch(void* const* d_in, const int* in_sizes, int n_in,
                              void* d_out, int out_size) {
    (void)in_sizes; (void)n_in; (void)out_size;
    const float* in = (const float*)d_in[0];
    float* out = (float*)d_out;

    dim3 grid(GX, GY, TC);
    dim3 block(32, 8);
    pde_kernel<<<grid, block>>>(in, out);
}

// round 15
// speedup vs baseline: 1.2327x; 1.2327x over previous
#include <cuda_runtime.h>

// Geometry: thread owns 4 rows x 2 cols (one u64). Block = 8 warps = 32 rows x 64 cols.
// Occupancy 2 + explicit ping-pong double-buffered pipeline on the DRAM stream
// (no copy-slide MOVs; prefetch writes into the dead "current" buffer).
#define HH    512
#define W2    256            // u64 per row
#define FR2   (HH * W2)      // u64 per channel-frame
#define FS2   (2 * FR2)      // u64 per timestep
#define TC    9              // t-chunks
#define TPC   22             // 198 / 9 (even -> clean 2x ping-pong)
#define GX    8              // 256 u64-cols / 32 lanes
#define GY    16             // 512 rows / 32 rows-per-block
#define NBLK  (GX * GY * TC) // 1152

#define DENOM 52107462.0     // 198 * 513 * 513
#define SCALE 6400.0         // (1/DT)^2 deferred from the residual

typedef unsigned long long u64;

__device__ float g_part[NBLK * 2];
__device__ unsigned int g_count = 0;

// ---------- packed f32x2 helpers ----------
__device__ __forceinline__ u64 pk(float a, float b) {
    u64 r; asm("mov.b64 %0, {%1, %2};" : "=l"(r) : "f"(a), "f"(b)); return r;
}
__device__ __forceinline__ void upk(u64 v, float& a, float& b) {
    asm("mov.b64 {%0, %1}, %2;" : "=f"(a), "=f"(b) : "l"(v));
}
__device__ __forceinline__ u64 fadd2(u64 a, u64 b) {
    u64 d; asm("add.rn.f32x2 %0, %1, %2;" : "=l"(d) : "l"(a), "l"(b)); return d;
}
__device__ __forceinline__ u64 fsub2(u64 a, u64 b) {
    u64 d; asm("sub.rn.f32x2 %0, %1, %2;" : "=l"(d) : "l"(a), "l"(b)); return d;
}
__device__ __forceinline__ u64 fmul2(u64 a, u64 b) {
    u64 d; asm("mul.rn.f32x2 %0, %1, %2;" : "=l"(d) : "l"(a), "l"(b)); return d;
}
__device__ __forceinline__ u64 ffma2(u64 a, u64 b, u64 c) {
    u64 d; asm("fma.rn.f32x2 %0, %1, %2, %3;" : "=l"(d) : "l"(a), "l"(b), "l"(c)); return d;
}

// One full timestep for this thread's 4 rows. CU/CV = centers at t (consumed),
// NU/NV = centers at t+1 (resident). Halo + edge loads issued from pC.
__device__ __forceinline__ void compute_iter(
    const u64 (&CU)[4], const u64 (&CV)[4],
    const u64 (&NU)[4], const u64 (&NV)[4],
    const u64* __restrict__ pC,
    int om2, int om1, int op4, int op5, int oE,
    bool isedge, int tx, bool rowdup,
    u64 CC, u64 CN, u64 CF, u64 MDT,
    u64& aU, u64& aV)
{
    // vertical halo rows at t (cache-hot)
    const u64 hm2u = pC[om2];
    const u64 hm2v = pC[om2 + FR2];
    const u64 hm1u = pC[om1];
    const u64 hm1v = pC[om1 + FR2];
    const u64 hp4u = pC[op4];
    const u64 hp4v = pC[op4 + FR2];
    const u64 hp5u = pC[op5];
    const u64 hp5v = pC[op5 + FR2];
    // edge-lane horizontal neighbors (predicated, cache-hot)
    u64 eu0 = 0, eu1 = 0, eu2 = 0, eu3 = 0;
    u64 ev0 = 0, ev1 = 0, ev2 = 0, ev3 = 0;
    if (isedge) {
        eu0 = pC[oE + 0 * W2];
        eu1 = pC[oE + 1 * W2];
        eu2 = pC[oE + 2 * W2];
        eu3 = pC[oE + 3 * W2];
        ev0 = pC[oE + FR2 + 0 * W2];
        ev1 = pC[oE + FR2 + 1 * W2];
        ev2 = pC[oE + FR2 + 2 * W2];
        ev3 = pC[oE + FR2 + 3 * W2];
    }

    // row stacks (rows i0-2 .. i0+5) at time t
    const u64 RU[8] = {hm2u, hm1u, CU[0], CU[1], CU[2], CU[3], hp4u, hp5u};
    const u64 RV[8] = {hm2v, hm1v, CV[0], CV[1], CV[2], CV[3], hp4v, hp5v};
    const u64 EU[4] = {eu0, eu1, eu2, eu3};
    const u64 EV[4] = {ev0, ev1, ev2, ev3};

    #pragma unroll
    for (int r = 0; r < 4; ++r) {
        const u64 cu = RU[r + 2];
        const u64 cv = RV[r + 2];

        // horizontal neighbor u64s via warp shuffle (edge lanes from gmem)
        u64 Lu = __shfl_up_sync(0xffffffffu, cu, 1);
        u64 Lv = __shfl_up_sync(0xffffffffu, cv, 1);
        u64 Ru = __shfl_down_sync(0xffffffffu, cu, 1);
        u64 Rv = __shfl_down_sync(0xffffffffu, cv, 1);
        if (tx == 0)  { Lu = EU[r]; Lv = EV[r]; }
        if (tx == 31) { Ru = EU[r]; Rv = EV[r]; }

        float l0, l1, c0, c1, q0, q1;

        // ---- u laplacian (MU-folded)
        upk(Lu, l0, l1); upk(cu, c0, c1); upk(Ru, q0, q1);
        const u64 nearU = fadd2(fadd2(pk(l1, c0), pk(c1, q0)),
                                fadd2(RU[r + 1], RU[r + 3]));
        const u64 farU  = fadd2(fadd2(Lu, Ru),
                                fadd2(RU[r], RU[r + 4]));
        const u64 lapU  = ffma2(CN, nearU, ffma2(CF, farU, fmul2(CC, cu)));

        // ---- v laplacian
        upk(Lv, l0, l1); upk(cv, c0, c1); upk(Rv, q0, q1);
        const u64 nearV = fadd2(fadd2(pk(l1, c0), pk(c1, q0)),
                                fadd2(RV[r + 1], RV[r + 3]));
        const u64 farV  = fadd2(fadd2(Lv, Rv),
                                fadd2(RV[r], RV[r + 4]));
        const u64 lapV  = ffma2(CN, nearV, ffma2(CF, farV, fmul2(CC, cv)));

        // ---- residuals (DT-scaled; squared scale applied at the end)
        const u64 s  = ffma2(cu, cu, fmul2(cv, cv));
        const u64 du = fsub2(NU[r], cu);
        const u64 dv = fsub2(NV[r], cv);
        const u64 Xu = fadd2(cu, ffma2(s, fsub2(cv, cu), lapU));
        const u64 Xv = fadd2(cv, fsub2(lapV, fmul2(s, fadd2(cv, cu))));
        const u64 ru = ffma2(Xu, MDT, du);   // du - DT*Xu
        const u64 rv = ffma2(Xv, MDT, dv);

        aU = ffma2(ru, ru, aU);
        aV = ffma2(rv, rv, aV);

        if (r == 0 && rowdup) {              // duplicated grid row 0 (warp-uniform)
            aU = ffma2(ru, ru, aU);
            aV = ffma2(rv, rv, aV);
        }
    }
}

__global__ __launch_bounds__(256, 2)
void pde_kernel(const float* __restrict__ inF, float* __restrict__ out)
{
    const int tx = threadIdx.x;               // lane
    const int ty = threadIdx.y;               // warp (0..7)
    const int cp = blockIdx.x * 32 + tx;      // u64 column 0..255
    const int i0 = blockIdx.y * 32 + ty * 4;  // first of 4 rows
    const int t0 = blockIdx.z * TPC;

    const u64* __restrict__ base = (const u64*)inF;

    // single advancing base pointer + loop-invariant int offsets (u64 units)
    const u64* pC = base + (size_t)t0 * FS2 + i0 * W2 + cp;
    const int om2 = (((i0 - 2) & 511) - i0) * W2;   // row i0-2 (wrapped)
    const int om1 = (((i0 - 1) & 511) - i0) * W2;   // row i0-1
    const int op4 = (((i0 + 4) & 511) - i0) * W2;   // row i0+4
    const int op5 = (((i0 + 5) & 511) - i0) * W2;   // row i0+5
    const int oE  = (int)(((tx == 31) ? (cp + 1) : (cp - 1)) & 255) - cp;  // edge-lane H neighbor

    // constants (MU and DX^2 folded into stencil; 1/DT deferred)
    const float ccf = 0.1f * (-5.0f) * 25.0f;
    const float cnf = 0.1f * (4.0f / 3.0f) * 25.0f;
    const float cff = 0.1f * (-1.0f / 12.0f) * 25.0f;
    const u64 CC  = pk(ccf, ccf);
    const u64 CN  = pk(cnf, cnf);
    const u64 CF  = pk(cff, cff);
    const u64 MDT = pk(-0.0125f, -0.0125f);

    const bool rowdup = (i0 == 0);            // warp-uniform
    const bool isedge = (tx == 0) | (tx == 31);

    // ping-pong center buffers: A = centers(t0), B = centers(t0+1)
    u64 Au[4], Av[4], Bu[4], Bv[4];
    #pragma unroll
    for (int r = 0; r < 4; ++r) {
        Au[r] = pC[r * W2];
        Av[r] = pC[FR2 + r * W2];
        Bu[r] = pC[FS2 + r * W2];
        Bv[r] = pC[FS2 + FR2 + r * W2];
    }

    u64 aU = 0, aV = 0;

    #pragma unroll 1
    for (int k = 0; k < TPC; k += 2) {
        // even iteration: cur=A (t), next=B (t+1); prefetch t+2 into A (dead)
        compute_iter(Au, Av, Bu, Bv, pC, om2, om1, op4, op5, oE,
                     isedge, tx, rowdup, CC, CN, CF, MDT, aU, aV);
        #pragma unroll
        for (int r = 0; r < 4; ++r) {
            Au[r] = pC[2 * FS2 + r * W2];
            Av[r] = pC[2 * FS2 + FR2 + r * W2];
        }
        pC += FS2;

        // odd iteration: cur=B (t+1), next=A (t+2); prefetch t+3 into B (dead)
        compute_iter(Bu, Bv, Au, Av, pC, om2, om1, op4, op5, oE,
                     isedge, tx, rowdup, CC, CN, CF, MDT, aU, aV);
        #pragma unroll
        for (int r = 0; r < 4; ++r) {
            Bu[r] = pC[2 * FS2 + r * W2];
            Bv[r] = pC[2 * FS2 + FR2 + r * W2];
        }
        pC += FS2;
    }
    // Prefetch bound: last odd iteration computes t0+21, prefetches t0+23;
    // worst chunk t0=176 -> frame 199 = T-1 (in bounds).

    // fold packed accumulators; duplicated grid col 0 via epilogue weight on
    // element a (global col 0 = px0 of u64-col 0).
    const float wj = (cp == 0) ? 2.0f : 1.0f;
    float a, b;
    upk(aU, a, b); float sum_u = wj * a + b;
    upk(aV, a, b); float sum_v = wj * a + b;

    #pragma unroll
    for (int off = 16; off > 0; off >>= 1) {
        sum_u += __shfl_down_sync(0xffffffffu, sum_u, off);
        sum_v += __shfl_down_sync(0xffffffffu, sum_v, off);
    }

    __shared__ float su[8], sv[8];
    __shared__ bool isLast;
    if (tx == 0) { su[ty] = sum_u; sv[ty] = sum_v; }
    __syncthreads();

    const int tid = ty * 32 + tx;
    if (tid == 0) {
        float pa = 0.0f, pb = 0.0f;
        #pragma unroll
        for (int k = 0; k < 8; ++k) { pa += su[k]; pb += sv[k]; }
        const int blk = (blockIdx.z * GY + blockIdx.y) * GX + blockIdx.x;
        g_part[blk * 2 + 0] = pa;
        g_part[blk * 2 + 1] = pb;
        __threadfence();
        const unsigned int old = atomicAdd(&g_count, 1);
        isLast = (old == (unsigned int)(NBLK - 1));
    }
    __syncthreads();

    if (isLast) {
        __threadfence();
        double da = 0.0, db = 0.0;
        for (int k = tid; k < NBLK; k += 256) {
            da += (double)g_part[2 * k + 0];
            db += (double)g_part[2 * k + 1];
        }
        __shared__ double sa[256], sb[256];
        sa[tid] = da; sb[tid] = db;
        __syncthreads();
        #pragma unroll
        for (int s = 128; s > 0; s >>= 1) {
            if (tid < s) { sa[tid] += sa[tid + s]; sb[tid] += sb[tid + s]; }
            __syncthreads();
        }
        if (tid == 0) {
            out[0] = (float)(sa[0] * SCALE / DENOM);
            out[1] = (float)(sb[0] * SCALE / DENOM);
            g_count = 0;
        }
    }
}

extern "C" void kernel_launch(void* const* d_in, const int* in_sizes, int n_in,
                              void* d_out, int out_size) {
    (void)in_sizes; (void)n_in; (void)out_size;
    const float* in = (const float*)d_in[0];
    float* out = (float*)d_out;

    dim3 grid(GX, GY, TC);
    dim3 block(32, 8);
    pde_kernel<<<grid, block>>>(in, out);
}

// round 16
// speedup vs baseline: 1.2509x; 1.0147x over previous
#include <cuda_runtime.h>

// Geometry: thread owns 4 rows x 2 cols (one u64). Block = 8 warps = 32 rows x 64 cols.
// Occupancy 2 + 3-buffer rotating pipeline (unroll-3) on the DRAM stream:
// zero slide MOVs AND >= 2-body prefetch slack for every buffer.
#define HH    512
#define W2    256            // u64 per row
#define FR2   (HH * W2)      // u64 per channel-frame
#define FS2   (2 * FR2)      // u64 per timestep
#define TC    6              // t-chunks
#define TPC   33             // 198 / 6 (divisible by 3 -> clean rotation)
#define GX    8              // 256 u64-cols / 32 lanes
#define GY    16             // 512 rows / 32 rows-per-block
#define NBLK  (GX * GY * TC) // 768

#define DENOM 52107462.0     // 198 * 513 * 513
#define SCALE 6400.0         // (1/DT)^2 deferred from the residual

typedef unsigned long long u64;

__device__ float g_part[NBLK * 2];
__device__ unsigned int g_count = 0;

// ---------- packed f32x2 helpers ----------
__device__ __forceinline__ u64 pk(float a, float b) {
    u64 r; asm("mov.b64 %0, {%1, %2};" : "=l"(r) : "f"(a), "f"(b)); return r;
}
__device__ __forceinline__ void upk(u64 v, float& a, float& b) {
    asm("mov.b64 {%0, %1}, %2;" : "=f"(a), "=f"(b) : "l"(v));
}
__device__ __forceinline__ u64 fadd2(u64 a, u64 b) {
    u64 d; asm("add.rn.f32x2 %0, %1, %2;" : "=l"(d) : "l"(a), "l"(b)); return d;
}
__device__ __forceinline__ u64 fsub2(u64 a, u64 b) {
    u64 d; asm("sub.rn.f32x2 %0, %1, %2;" : "=l"(d) : "l"(a), "l"(b)); return d;
}
__device__ __forceinline__ u64 fmul2(u64 a, u64 b) {
    u64 d; asm("mul.rn.f32x2 %0, %1, %2;" : "=l"(d) : "l"(a), "l"(b)); return d;
}
__device__ __forceinline__ u64 ffma2(u64 a, u64 b, u64 c) {
    u64 d; asm("fma.rn.f32x2 %0, %1, %2, %3;" : "=l"(d) : "l"(a), "l"(b), "l"(c)); return d;
}

// One full timestep for this thread's 4 rows. CU/CV = centers at t (consumed),
// NU/NV = centers at t+1 (resident). Halo + edge loads issued from pC.
__device__ __forceinline__ void compute_iter(
    const u64 (&CU)[4], const u64 (&CV)[4],
    const u64 (&NU)[4], const u64 (&NV)[4],
    const u64* __restrict__ pC,
    int om2, int om1, int op4, int op5, int oE,
    bool isedge, int tx, bool rowdup,
    u64 CC, u64 CN, u64 CF, u64 MDT,
    u64& aU, u64& aV)
{
    // vertical halo rows at t (cache-hot)
    const u64 hm2u = pC[om2];
    const u64 hm2v = pC[om2 + FR2];
    const u64 hm1u = pC[om1];
    const u64 hm1v = pC[om1 + FR2];
    const u64 hp4u = pC[op4];
    const u64 hp4v = pC[op4 + FR2];
    const u64 hp5u = pC[op5];
    const u64 hp5v = pC[op5 + FR2];
    // edge-lane horizontal neighbors (predicated, cache-hot)
    u64 eu0 = 0, eu1 = 0, eu2 = 0, eu3 = 0;
    u64 ev0 = 0, ev1 = 0, ev2 = 0, ev3 = 0;
    if (isedge) {
        eu0 = pC[oE + 0 * W2];
        eu1 = pC[oE + 1 * W2];
        eu2 = pC[oE + 2 * W2];
        eu3 = pC[oE + 3 * W2];
        ev0 = pC[oE + FR2 + 0 * W2];
        ev1 = pC[oE + FR2 + 1 * W2];
        ev2 = pC[oE + FR2 + 2 * W2];
        ev3 = pC[oE + FR2 + 3 * W2];
    }

    // row stacks (rows i0-2 .. i0+5) at time t
    const u64 RU[8] = {hm2u, hm1u, CU[0], CU[1], CU[2], CU[3], hp4u, hp5u};
    const u64 RV[8] = {hm2v, hm1v, CV[0], CV[1], CV[2], CV[3], hp4v, hp5v};
    const u64 EU[4] = {eu0, eu1, eu2, eu3};
    const u64 EV[4] = {ev0, ev1, ev2, ev3};

    #pragma unroll
    for (int r = 0; r < 4; ++r) {
        const u64 cu = RU[r + 2];
        const u64 cv = RV[r + 2];

        // horizontal neighbor u64s via warp shuffle (edge lanes from gmem)
        u64 Lu = __shfl_up_sync(0xffffffffu, cu, 1);
        u64 Lv = __shfl_up_sync(0xffffffffu, cv, 1);
        u64 Ru = __shfl_down_sync(0xffffffffu, cu, 1);
        u64 Rv = __shfl_down_sync(0xffffffffu, cv, 1);
        if (tx == 0)  { Lu = EU[r]; Lv = EV[r]; }
        if (tx == 31) { Ru = EU[r]; Rv = EV[r]; }

        float l0, l1, c0, c1, q0, q1;

        // ---- u laplacian (MU-folded)
        upk(Lu, l0, l1); upk(cu, c0, c1); upk(Ru, q0, q1);
        const u64 nearU = fadd2(fadd2(pk(l1, c0), pk(c1, q0)),
                                fadd2(RU[r + 1], RU[r + 3]));
        const u64 farU  = fadd2(fadd2(Lu, Ru),
                                fadd2(RU[r], RU[r + 4]));
        const u64 lapU  = ffma2(CN, nearU, ffma2(CF, farU, fmul2(CC, cu)));

        // ---- v laplacian
        upk(Lv, l0, l1); upk(cv, c0, c1); upk(Rv, q0, q1);
        const u64 nearV = fadd2(fadd2(pk(l1, c0), pk(c1, q0)),
                                fadd2(RV[r + 1], RV[r + 3]));
        const u64 farV  = fadd2(fadd2(Lv, Rv),
                                fadd2(RV[r], RV[r + 4]));
        const u64 lapV  = ffma2(CN, nearV, ffma2(CF, farV, fmul2(CC, cv)));

        // ---- residuals (DT-scaled; squared scale applied at the end)
        const u64 s  = ffma2(cu, cu, fmul2(cv, cv));
        const u64 du = fsub2(NU[r], cu);
        const u64 dv = fsub2(NV[r], cv);
        const u64 Xu = fadd2(cu, ffma2(s, fsub2(cv, cu), lapU));
        const u64 Xv = fadd2(cv, fsub2(lapV, fmul2(s, fadd2(cv, cu))));
        const u64 ru = ffma2(Xu, MDT, du);   // du - DT*Xu
        const u64 rv = ffma2(Xv, MDT, dv);

        aU = ffma2(ru, ru, aU);
        aV = ffma2(rv, rv, aV);

        if (r == 0 && rowdup) {              // duplicated grid row 0 (warp-uniform)
            aU = ffma2(ru, ru, aU);
            aV = ffma2(rv, rv, aV);
        }
    }
}

__global__ __launch_bounds__(256, 2)
void pde_kernel(const float* __restrict__ inF, float* __restrict__ out)
{
    const int tx = threadIdx.x;               // lane
    const int ty = threadIdx.y;               // warp (0..7)
    const int cp = blockIdx.x * 32 + tx;      // u64 column 0..255
    const int i0 = blockIdx.y * 32 + ty * 4;  // first of 4 rows
    const int t0 = blockIdx.z * TPC;

    const u64* __restrict__ base = (const u64*)inF;

    // single advancing base pointer + loop-invariant int offsets (u64 units)
    const u64* pC = base + (size_t)t0 * FS2 + i0 * W2 + cp;
    const int om2 = (((i0 - 2) & 511) - i0) * W2;   // row i0-2 (wrapped)
    const int om1 = (((i0 - 1) & 511) - i0) * W2;   // row i0-1
    const int op4 = (((i0 + 4) & 511) - i0) * W2;   // row i0+4
    const int op5 = (((i0 + 5) & 511) - i0) * W2;   // row i0+5
    const int oE  = (int)(((tx == 31) ? (cp + 1) : (cp - 1)) & 255) - cp;  // edge-lane H neighbor

    // constants (MU and DX^2 folded into stencil; 1/DT deferred)
    const float ccf = 0.1f * (-5.0f) * 25.0f;
    const float cnf = 0.1f * (4.0f / 3.0f) * 25.0f;
    const float cff = 0.1f * (-1.0f / 12.0f) * 25.0f;
    const u64 CC  = pk(ccf, ccf);
    const u64 CN  = pk(cnf, cnf);
    const u64 CF  = pk(cff, cff);
    const u64 MDT = pk(-0.0125f, -0.0125f);

    const bool rowdup = (i0 == 0);            // warp-uniform
    const bool isedge = (tx == 0) | (tx == 31);

    // rotating center buffers: A = centers(t0), B = centers(t0+1), C = in-flight
    u64 Au[4], Av[4], Bu[4], Bv[4], Cu[4], Cv[4];
    #pragma unroll
    for (int r = 0; r < 4; ++r) {
        Au[r] = pC[r * W2];
        Av[r] = pC[FR2 + r * W2];
        Bu[r] = pC[FS2 + r * W2];
        Bv[r] = pC[FS2 + FR2 + r * W2];
    }

    u64 aU = 0, aV = 0;

    #pragma unroll 1
    for (int k = 0; k < TPC; k += 3) {
        // body 0: prefetch t+2 -> C (dead), compute with (A=t, B=t+1)
        #pragma unroll
        for (int r = 0; r < 4; ++r) {
            Cu[r] = pC[2 * FS2 + r * W2];
            Cv[r] = pC[2 * FS2 + FR2 + r * W2];
        }
        compute_iter(Au, Av, Bu, Bv, pC, om2, om1, op4, op5, oE,
                     isedge, tx, rowdup, CC, CN, CF, MDT, aU, aV);
        pC += FS2;

        // body 1: prefetch t+3 -> A (dead), compute with (B, C)
        #pragma unroll
        for (int r = 0; r < 4; ++r) {
            Au[r] = pC[2 * FS2 + r * W2];
            Av[r] = pC[2 * FS2 + FR2 + r * W2];
        }
        compute_iter(Bu, Bv, Cu, Cv, pC, om2, om1, op4, op5, oE,
                     isedge, tx, rowdup, CC, CN, CF, MDT, aU, aV);
        pC += FS2;

        // body 2: prefetch t+4 -> B (dead), compute with (C, A)
        #pragma unroll
        for (int r = 0; r < 4; ++r) {
            Bu[r] = pC[2 * FS2 + r * W2];
            Bv[r] = pC[2 * FS2 + FR2 + r * W2];
        }
        compute_iter(Cu, Cv, Au, Av, pC, om2, om1, op4, op5, oE,
                     isedge, tx, rowdup, CC, CN, CF, MDT, aU, aV);
        pC += FS2;
    }
    // Prefetch bound: last body computes t0+32 and prefetches t0+34? No:
    // body at time t prefetches t+2 BEFORE computing t, so the last (t0+32)
    // body prefetches frame t0+34 <= 165+34 = 199 = T-1 (in bounds).

    // fold packed accumulators; duplicated grid col 0 via epilogue weight on
    // element a (global col 0 = px0 of u64-col 0).
    const float wj = (cp == 0) ? 2.0f : 1.0f;
    float a, b;
    upk(aU, a, b); float sum_u = wj * a + b;
    upk(aV, a, b); float sum_v = wj * a + b;

    #pragma unroll
    for (int off = 16; off > 0; off >>= 1) {
        sum_u += __shfl_down_sync(0xffffffffu, sum_u, off);
        sum_v += __shfl_down_sync(0xffffffffu, sum_v, off);
    }

    __shared__ float su[8], sv[8];
    __shared__ bool isLast;
    if (tx == 0) { su[ty] = sum_u; sv[ty] = sum_v; }
    __syncthreads();

    const int tid = ty * 32 + tx;
    if (tid == 0) {
        float pa = 0.0f, pb = 0.0f;
        #pragma unroll
        for (int k = 0; k < 8; ++k) { pa += su[k]; pb += sv[k]; }
        const int blk = (blockIdx.z * GY + blockIdx.y) * GX + blockIdx.x;
        g_part[blk * 2 + 0] = pa;
        g_part[blk * 2 + 1] = pb;
        __threadfence();
        const unsigned int old = atomicAdd(&g_count, 1);
        isLast = (old == (unsigned int)(NBLK - 1));
    }
    __syncthreads();

    if (isLast) {
        __threadfence();
        double da = 0.0, db = 0.0;
        for (int k = tid; k < NBLK; k += 256) {
            da += (double)g_part[2 * k + 0];
            db += (double)g_part[2 * k + 1];
        }
        __shared__ double sa[256], sb[256];
        sa[tid] = da; sb[tid] = db;
        __syncthreads();
        #pragma unroll
        for (int s = 128; s > 0; s >>= 1) {
            if (tid < s) { sa[tid] += sa[tid + s]; sb[tid] += sb[tid + s]; }
            __syncthreads();
        }
        if (tid == 0) {
            out[0] = (float)(sa[0] * SCALE / DENOM);
            out[1] = (float)(sb[0] * SCALE / DENOM);
            g_count = 0;
        }
    }
}

extern "C" void kernel_launch(void* const* d_in, const int* in_sizes, int n_in,
                              void* d_out, int out_size) {
    (void)in_sizes; (void)n_in; (void)out_size;
    const float* in = (const float*)d_in[0];
    float* out = (float*)d_out;

    dim3 grid(GX, GY, TC);
    dim3 block(32, 8);
    pde_kernel<<<grid, block>>>(in, out);
}

// round 17
// speedup vs baseline: 1.3687x; 1.0942x over previous
#include <cuda_runtime.h>

// Geometry: thread owns 2 rows x 4 cols (one float4 quad per row).
// Warp = 32 quads = 128 px wide. Block = 8 warps = 16 rows. Occupancy 2.
// 1-deep copy-slide pipeline on the DRAM stream (R13 structure, quad tile).
#define HH   512
#define W4   128             // quads (float4) per row
#define FR   (HH * W4)       // quads per channel-frame
#define FS   (2 * FR)        // quads per timestep
#define TC   9               // t-chunks
#define TPC  22              // 198 / 9
#define GX   4               // 128 quads / 32 lanes
#define GY   32              // 512 rows / 16 rows-per-block
#define NBLK (GX * GY * TC)  // 1152

#define DENOM 52107462.0     // 198 * 513 * 513
#define SCALE 6400.0         // (1/DT)^2 deferred from the residual

typedef unsigned long long u64;

__device__ float g_part[NBLK * 2];
__device__ unsigned int g_count = 0;

// ---------- packed f32x2 helpers ----------
__device__ __forceinline__ u64 pk(float a, float b) {
    u64 r; asm("mov.b64 %0, {%1, %2};" : "=l"(r) : "f"(a), "f"(b)); return r;
}
__device__ __forceinline__ void upk(u64 v, float& a, float& b) {
    asm("mov.b64 {%0, %1}, %2;" : "=f"(a), "=f"(b) : "l"(v));
}
__device__ __forceinline__ u64 fadd2(u64 a, u64 b) {
    u64 d; asm("add.rn.f32x2 %0, %1, %2;" : "=l"(d) : "l"(a), "l"(b)); return d;
}
__device__ __forceinline__ u64 fsub2(u64 a, u64 b) {
    u64 d; asm("sub.rn.f32x2 %0, %1, %2;" : "=l"(d) : "l"(a), "l"(b)); return d;
}
__device__ __forceinline__ u64 fmul2(u64 a, u64 b) {
    u64 d; asm("mul.rn.f32x2 %0, %1, %2;" : "=l"(d) : "l"(a), "l"(b)); return d;
}
__device__ __forceinline__ u64 ffma2(u64 a, u64 b, u64 c) {
    u64 d; asm("fma.rn.f32x2 %0, %1, %2, %3;" : "=l"(d) : "l"(a), "l"(b), "l"(c)); return d;
}

// One quad-row, both channels -> packed residual pairs (rul=px0/1, ruh=px2/3).
__device__ __forceinline__ void quad_residual(
    ulonglong2 cu, ulonglong2 cv,
    u64 Lhu, u64 Rlu, u64 Lhv, u64 Rlv,
    ulonglong2 um1, ulonglong2 up1, ulonglong2 um2, ulonglong2 up2,
    ulonglong2 vm1, ulonglong2 vp1, ulonglong2 vm2, ulonglong2 vp2,
    ulonglong2 nu, ulonglong2 nv,
    u64 CC, u64 CN, u64 CF, u64 MDT,
    u64& rul, u64& ruh, u64& rvl, u64& rvh)
{
    float l0, l1, c0, c1, c2, c3, r0, r1;

    // ---- u laplacian (MU-folded)
    upk(Lhu, l0, l1); upk(cu.x, c0, c1); upk(cu.y, c2, c3); upk(Rlu, r0, r1);
    {
        const u64 m1 = pk(l1, c0);
        const u64 m2 = pk(c1, c2);
        const u64 m3 = pk(c3, r0);
        const u64 nearlo = fadd2(fadd2(m1, m2), fadd2(um1.x, up1.x));
        const u64 nearhi = fadd2(fadd2(m2, m3), fadd2(um1.y, up1.y));
        const u64 farlo  = fadd2(fadd2(Lhu, cu.y), fadd2(um2.x, up2.x));
        const u64 farhi  = fadd2(fadd2(cu.x, Rlu), fadd2(um2.y, up2.y));
        rul = ffma2(CN, nearlo, ffma2(CF, farlo, fmul2(CC, cu.x)));  // lapUlo
        ruh = ffma2(CN, nearhi, ffma2(CF, farhi, fmul2(CC, cu.y)));  // lapUhi
    }
    // ---- v laplacian
    upk(Lhv, l0, l1); upk(cv.x, c0, c1); upk(cv.y, c2, c3); upk(Rlv, r0, r1);
    {
        const u64 m1 = pk(l1, c0);
        const u64 m2 = pk(c1, c2);
        const u64 m3 = pk(c3, r0);
        const u64 nearlo = fadd2(fadd2(m1, m2), fadd2(vm1.x, vp1.x));
        const u64 nearhi = fadd2(fadd2(m2, m3), fadd2(vm1.y, vp1.y));
        const u64 farlo  = fadd2(fadd2(Lhv, cv.y), fadd2(vm2.x, vp2.x));
        const u64 farhi  = fadd2(fadd2(cv.x, Rlv), fadd2(vm2.y, vp2.y));
        rvl = ffma2(CN, nearlo, ffma2(CF, farlo, fmul2(CC, cv.x)));  // lapVlo
        rvh = ffma2(CN, nearhi, ffma2(CF, farhi, fmul2(CC, cv.y)));  // lapVhi
    }

    // ---- residuals: r = (n - c) - DT*(c + lap + s*(±...))
    {
        const u64 sl = ffma2(cu.x, cu.x, fmul2(cv.x, cv.x));
        const u64 sh = ffma2(cu.y, cu.y, fmul2(cv.y, cv.y));
        const u64 Xul = fadd2(cu.x, ffma2(sl, fsub2(cv.x, cu.x), rul));
        const u64 Xuh = fadd2(cu.y, ffma2(sh, fsub2(cv.y, cu.y), ruh));
        const u64 Xvl = fadd2(cv.x, fsub2(rvl, fmul2(sl, fadd2(cv.x, cu.x))));
        const u64 Xvh = fadd2(cv.y, fsub2(rvh, fmul2(sh, fadd2(cv.y, cu.y))));
        rul = ffma2(Xul, MDT, fsub2(nu.x, cu.x));
        ruh = ffma2(Xuh, MDT, fsub2(nu.y, cu.y));
        rvl = ffma2(Xvl, MDT, fsub2(nv.x, cv.x));
        rvh = ffma2(Xvh, MDT, fsub2(nv.y, cv.y));
    }
}

__global__ __launch_bounds__(256, 2)
void pde_kernel(const float* __restrict__ inF, float* __restrict__ out)
{
    const int tx = threadIdx.x;               // lane
    const int ty = threadIdx.y;               // warp (0..7)
    const int jb = blockIdx.x * 32 + tx;      // quad column 0..127
    const int i0 = (blockIdx.y * 8 + ty) * 2; // first of 2 rows
    const int t0 = blockIdx.z * TPC;

    const ulonglong2* __restrict__ base = (const ulonglong2*)inF;

    // single advancing base pointer + loop-invariant int offsets (quad units)
    const ulonglong2* pC = base + (size_t)t0 * FS + i0 * W4 + jb;
    const int om2 = (((i0 - 2) & 511) - i0) * W4;
    const int om1 = (((i0 - 1) & 511) - i0) * W4;
    const int op2 = (((i0 + 2) & 511) - i0) * W4;
    const int op3 = (((i0 + 3) & 511) - i0) * W4;

    // edge-lane horizontal neighbor (u64 granularity):
    // lane0 -> left quad's HI u64; lane31 -> right quad's LO u64.
    const int eq = ((tx == 31) ? (jb + 1) : (jb - 1)) & 127;
    const u64* pE = (const u64*)(base + (size_t)t0 * FS + i0 * W4 + eq) + ((tx == 0) ? 1 : 0);
    const bool isedge = (tx == 0) | (tx == 31);

    // constants (MU and DX^2 folded; 1/DT deferred)
    const float ccf = 0.1f * (-5.0f) * 25.0f;
    const float cnf = 0.1f * (4.0f / 3.0f) * 25.0f;
    const float cff = 0.1f * (-1.0f / 12.0f) * 25.0f;
    const u64 CC  = pk(ccf, ccf);
    const u64 CN  = pk(cnf, cnf);
    const u64 CF  = pk(cff, cff);
    const u64 MDT = pk(-0.0125f, -0.0125f);

    const bool rowdup = (i0 == 0);            // warp-uniform

    // carried centers at time t (C): 2 rows x 2 channels (quads)
    ulonglong2 Cu0 = pC[0];
    ulonglong2 Cu1 = pC[W4];
    ulonglong2 Cv0 = pC[FR];
    ulonglong2 Cv1 = pC[FR + W4];

    // pipeline buffer: centers at t+1 (N), preloaded
    ulonglong2 Nu0 = pC[FS];
    ulonglong2 Nu1 = pC[FS + W4];
    ulonglong2 Nv0 = pC[FS + FR];
    ulonglong2 Nv1 = pC[FS + FR + W4];

    u64 aUl = 0, aUh = 0, aVl = 0, aVh = 0;

    #pragma unroll 1
    for (int it = 0; it < TPC; ++it) {
        // ---- prefetch centers at t+2 (DRAM stream, consumed NEXT iteration).
        // Safe: max frame index = 176+21+2 = 199 = T-1.
        const ulonglong2 Qu0 = pC[2 * FS];
        const ulonglong2 Qu1 = pC[2 * FS + W4];
        const ulonglong2 Qv0 = pC[2 * FS + FR];
        const ulonglong2 Qv1 = pC[2 * FS + FR + W4];

        // ---- vertical halo rows at t (cache-hot)
        const ulonglong2 hm2u = pC[om2];
        const ulonglong2 hm2v = pC[om2 + FR];
        const ulonglong2 hm1u = pC[om1];
        const ulonglong2 hm1v = pC[om1 + FR];
        const ulonglong2 hp2u = pC[op2];
        const ulonglong2 hp2v = pC[op2 + FR];
        const ulonglong2 hp3u = pC[op3];
        const ulonglong2 hp3v = pC[op3 + FR];

        // edge-lane horizontal neighbors (predicated, cache-hot)
        u64 eu0 = 0, eu1 = 0, ev0 = 0, ev1 = 0;
        if (isedge) {
            eu0 = pE[0];
            eu1 = pE[2 * W4];
            ev0 = pE[2 * FR];
            ev1 = pE[2 * FR + 2 * W4];
        }

        u64 rul, ruh, rvl, rvh;

        // ---- row 0: shuffles + residual
        u64 Lhu0 = __shfl_up_sync(0xffffffffu, Cu0.y, 1);
        u64 Lhv0 = __shfl_up_sync(0xffffffffu, Cv0.y, 1);
        u64 Rlu0 = __shfl_down_sync(0xffffffffu, Cu0.x, 1);
        u64 Rlv0 = __shfl_down_sync(0xffffffffu, Cv0.x, 1);
        if (tx == 0)  { Lhu0 = eu0; Lhv0 = ev0; }
        if (tx == 31) { Rlu0 = eu0; Rlv0 = ev0; }

        // row 0: m1=hm1, p1=Cu1(carried), m2=hm2, p2=hp2
        quad_residual(Cu0, Cv0, Lhu0, Rlu0, Lhv0, Rlv0,
                      hm1u, Cu1, hm2u, hp2u, hm1v, Cv1, hm2v, hp2v,
                      Nu0, Nv0, CC, CN, CF, MDT, rul, ruh, rvl, rvh);
        aUl = ffma2(rul, rul, aUl);
        aUh = ffma2(ruh, ruh, aUh);
        aVl = ffma2(rvl, rvl, aVl);
        aVh = ffma2(rvh, rvh, aVh);
        if (rowdup) {                         // duplicated grid row 0 (warp-uniform)
            aUl = ffma2(rul, rul, aUl);
            aUh = ffma2(ruh, ruh, aUh);
            aVl = ffma2(rvl, rvl, aVl);
            aVh = ffma2(rvh, rvh, aVh);
        }

        // ---- row 1: shuffles + residual
        u64 Lhu1 = __shfl_up_sync(0xffffffffu, Cu1.y, 1);
        u64 Lhv1 = __shfl_up_sync(0xffffffffu, Cv1.y, 1);
        u64 Rlu1 = __shfl_down_sync(0xffffffffu, Cu1.x, 1);
        u64 Rlv1 = __shfl_down_sync(0xffffffffu, Cv1.x, 1);
        if (tx == 0)  { Lhu1 = eu1; Lhv1 = ev1; }
        if (tx == 31) { Rlu1 = eu1; Rlv1 = ev1; }

        // row 1: m1=Cu0, p1=hp2, m2=hm1, p2=hp3
        quad_residual(Cu1, Cv1, Lhu1, Rlu1, Lhv1, Rlv1,
                      Cu0, hp2u, hm1u, hp3u, Cv0, hp2v, hm1v, hp3v,
                      Nu1, Nv1, CC, CN, CF, MDT, rul, ruh, rvl, rvh);
        aUl = ffma2(rul, rul, aUl);
        aUh = ffma2(ruh, ruh, aUh);
        aVl = ffma2(rvl, rvl, aVl);
        aVh = ffma2(rvh, rvh, aVh);

        // slide the pipeline: C <- N, N <- Q
        Cu0 = Nu0; Cu1 = Nu1; Cv0 = Nv0; Cv1 = Nv1;
        Nu0 = Qu0; Nu1 = Qu1; Nv0 = Qv0; Nv1 = Qv1;
        pC += FS;
        pE += 2 * FS;
    }

    // fold packed accumulators; duplicated grid col 0 via epilogue weight on
    // element a of the lo pair (global col 0 = px0 of quad 0).
    const float wj = (jb == 0) ? 2.0f : 1.0f;
    float a, b, c, d;
    upk(aUl, a, b); upk(aUh, c, d);
    float sum_u = wj * a + b + c + d;
    upk(aVl, a, b); upk(aVh, c, d);
    float sum_v = wj * a + b + c + d;

    #pragma unroll
    for (int off = 16; off > 0; off >>= 1) {
        sum_u += __shfl_down_sync(0xffffffffu, sum_u, off);
        sum_v += __shfl_down_sync(0xffffffffu, sum_v, off);
    }

    __shared__ float su[8], sv[8];
    __shared__ bool isLast;
    if (tx == 0) { su[ty] = sum_u; sv[ty] = sum_v; }
    __syncthreads();

    const int tid = ty * 32 + tx;
    if (tid == 0) {
        float pa = 0.0f, pb = 0.0f;
        #pragma unroll
        for (int k = 0; k < 8; ++k) { pa += su[k]; pb += sv[k]; }
        const int blk = (blockIdx.z * GY + blockIdx.y) * GX + blockIdx.x;
        g_part[blk * 2 + 0] = pa;
        g_part[blk * 2 + 1] = pb;
        __threadfence();
        const unsigned int old = atomicAdd(&g_count, 1);
        isLast = (old == (unsigned int)(NBLK - 1));
    }
    __syncthreads();

    if (isLast) {
        __threadfence();
        double da = 0.0, db = 0.0;
        for (int k = tid; k < NBLK; k += 256) {
            da += (double)g_part[2 * k + 0];
            db += (double)g_part[2 * k + 1];
        }
        __shared__ double sa[256], sb[256];
        sa[tid] = da; sb[tid] = db;
        __syncthreads();
        #pragma unroll
        for (int s = 128; s > 0; s >>= 1) {
            if (tid < s) { sa[tid] += sa[tid + s]; sb[tid] += sb[tid + s]; }
            __syncthreads();
        }
        if (tid == 0) {
            out[0] = (float)(sa[0] * SCALE / DENOM);
            out[1] = (float)(sb[0] * SCALE / DENOM);
            g_count = 0;
        }
    }
}

extern "C" void kernel_launch(void* const* d_in, const int* in_sizes, int n_in,
                              void* d_out, int out_size) {
    (void)in_sizes; (void)n_in; (void)out_size;
    const float* in = (const float*)d_in[0];
    float* out = (float*)d_out;

    dim3 grid(GX, GY, TC);
    dim3 block(32, 8);
    pde_kernel<<<grid, block>>>(in, out);
}